// round 1
// baseline (speedup 1.0000x reference)
#include <cuda_runtime.h>

#define FULLMASK 0xffffffffu

static constexpr int B_ = 65536;
static constexpr int OBS = 85;

// ---- shared memory layout (in floats) ----
static constexpr int OFF_WIN  = 0;                  // 3 * 8*64 = 1536
static constexpr int OFF_BIN  = OFF_WIN  + 1536;    // 3 * 64   = 192
static constexpr int OFF_WA   = OFF_BIN  + 192;     // 128 (Wa1|Wa2)
static constexpr int OFF_WO1  = OFF_WA   + 128;     // 10*32 = 320
static constexpr int OFF_BO1  = OFF_WO1  + 320;     // 32
static constexpr int OFF_WO2  = OFF_BO1  + 32;      // 32*16 = 512
static constexpr int OFF_BO2  = OFF_WO2  + 512;     // 16
static constexpr int OFF_WO3  = OFF_BO2  + 16;      // 16
static constexpr int OFF_BO3  = OFF_WO3  + 16;      // 1 (pad to 16)
static constexpr int OFF_WFC1 = OFF_BO3  + 16;      // 90*64 = 5760
static constexpr int OFF_BFC1 = OFF_WFC1 + 5760;    // 64
static constexpr int OFF_WIHT = OFF_BFC1 + 64;      // 64*192 = 12288 (transposed)
static constexpr int OFF_WHHT = OFF_WIHT + 12288;   // 12288 (transposed)
static constexpr int OFF_BIH  = OFF_WHHT + 12288;   // 192
static constexpr int OFF_BHH  = OFF_BIH  + 192;     // 192
static constexpr int OFF_WFC2 = OFF_BHH  + 192;     // 64*5 = 320
static constexpr int OFF_BFC2 = OFF_WFC2 + 320;     // 5 (pad to 16)
static constexpr int OFF_SCR  = OFF_BFC2 + 16;      // 12 warps * 512 floats
static constexpr int SCR_PER_WARP = 512;
static constexpr int SMEM_FLOATS = OFF_SCR + 12 * SCR_PER_WARP;
static constexpr int SMEM_BYTES  = SMEM_FLOATS * 4;

__device__ __forceinline__ float leaky(float x) { return x > 0.f ? x : 0.01f * x; }
__device__ __forceinline__ float sigm(float x)  { return __fdividef(1.f, 1.f + __expf(-x)); }
__device__ __forceinline__ float tanh_(float x) { return __fdividef(2.f, 1.f + __expf(-2.f * x)) - 1.f; }

__global__ void __launch_bounds__(384, 1)
atom_rnn_fused(const float* __restrict__ obs, const float* __restrict__ hidden,
               const float* __restrict__ w_in0, const float* __restrict__ b_in0,
               const float* __restrict__ w_in1, const float* __restrict__ b_in1,
               const float* __restrict__ w_in2, const float* __restrict__ b_in2,
               const float* __restrict__ W_,    const float* __restrict__ a_,
               const float* __restrict__ w_o1,  const float* __restrict__ b_o1,
               const float* __restrict__ w_o2,  const float* __restrict__ b_o2,
               const float* __restrict__ w_o3,  const float* __restrict__ b_o3,
               const float* __restrict__ w_fc1, const float* __restrict__ b_fc1,
               const float* __restrict__ w_ih,  const float* __restrict__ w_hh,
               const float* __restrict__ b_ih,  const float* __restrict__ b_hh,
               const float* __restrict__ w_fc2, const float* __restrict__ b_fc2,
               float* __restrict__ outq, float* __restrict__ outh)
{
    extern __shared__ float smem[];
    const int tid = threadIdx.x;

    // ================= cooperative weight staging (once per persistent block) ==========
    for (int i = tid; i < 512; i += 384) {
        smem[OFF_WIN + i]        = w_in0[i];
        smem[OFF_WIN + 512 + i]  = w_in1[i];
        smem[OFF_WIN + 1024 + i] = w_in2[i];
        smem[OFF_WO2 + i]        = w_o2[i];
    }
    for (int i = tid; i < 64; i += 384) {
        smem[OFF_BIN + i]       = b_in0[i];
        smem[OFF_BIN + 64 + i]  = b_in1[i];
        smem[OFF_BIN + 128 + i] = b_in2[i];
        smem[OFF_BFC1 + i]      = b_fc1[i];
    }
    if (tid < 128) { // Wa1[k] = sum_c W[k][c]*a[c] ; Wa2[k] = sum_c W[k][c]*a[64+c]
        int sel = tid >> 6, k = tid & 63;
        const float* av = a_ + sel * 64;
        const float* Wr = W_ + k * 64;
        float s = 0.f;
        #pragma unroll 8
        for (int c = 0; c < 64; c++) s += Wr[c] * av[c];
        smem[OFF_WA + sel * 64 + k] = s;
    }
    for (int i = tid; i < 320; i += 384) { smem[OFF_WO1 + i] = w_o1[i]; smem[OFF_WFC2 + i] = w_fc2[i]; }
    if (tid < 32) smem[OFF_BO1 + tid] = b_o1[tid];
    if (tid < 16) { smem[OFF_BO2 + tid] = b_o2[tid]; smem[OFF_WO3 + tid] = w_o3[tid]; }
    if (tid == 0) smem[OFF_BO3] = b_o3[0];
    if (tid < 5)  smem[OFF_BFC2 + tid] = b_fc2[tid];
    for (int i = tid; i < 5760; i += 384) smem[OFF_WFC1 + i] = w_fc1[i];
    for (int i = tid; i < 12288; i += 384) {
        int j = i >> 6, k = i & 63;              // w_ih[j][k] -> transposed [k][j]
        smem[OFF_WIHT + k * 192 + j] = w_ih[i];
        smem[OFF_WHHT + k * 192 + j] = w_hh[i];
    }
    for (int i = tid; i < 192; i += 384) { smem[OFF_BIH + i] = b_ih[i]; smem[OFF_BHH + i] = b_hh[i]; }
    __syncthreads();

    const int l    = tid & 31;
    const int warp = tid >> 5;
    float* scr = smem + OFF_SCR + warp * SCR_PER_WARP;
    const int gwid = blockIdx.x * 12 + warp;
    const int nw   = gridDim.x * 12;

    // load loop-invariant Wa values into registers
    const float wa10 = smem[OFF_WA + l],      wa11 = smem[OFF_WA + 32 + l];
    const float wa20 = smem[OFF_WA + 64 + l], wa21 = smem[OFF_WA + 96 + l];

    for (int p = gwid; p < B_ / 2; p += nw) {
        const int e0 = p * 2; // this warp processes elements e0 and e0+1

        // ---------- obs load: lane l holds obs[idx] for idx = l, l+32, l+64 ----------
        float ob[2][3];
        #pragma unroll
        for (int e = 0; e < 2; e++) {
            const float* orow = obs + (size_t)(e0 + e) * OBS;
            #pragma unroll
            for (int s = 0; s < 3; s++) {
                int idx = s * 32 + l;
                ob[e][s] = (idx < OBS) ? orow[idx] : 0.f;
            }
        }

        // ---------- stage 1: per-token selected input layer -> h_mix (lane: cols l, l+32)
        float hm[2][2][10];
        #pragma unroll
        for (int t = 0; t < 10; t++) {
            const int sel = (t < 5) ? 0 : ((t < 9) ? 1 : 2);
            const float* wsel = smem + OFF_WIN + sel * 512;
            float a00 = smem[OFF_BIN + sel * 64 + l];
            float a01 = smem[OFF_BIN + sel * 64 + 32 + l];
            float a10 = a00, a11 = a01;
            #pragma unroll
            for (int f = 0; f < 8; f++) {
                const int ii = (t * 8 + f + 4) % 80;   // obs_in rotation (compile-time)
                float w0 = wsel[f * 64 + l];
                float w1 = wsel[f * 64 + 32 + l];
                float v0 = __shfl_sync(FULLMASK, ob[0][ii >> 5], ii & 31);
                float v1 = __shfl_sync(FULLMASK, ob[1][ii >> 5], ii & 31);
                a00 += v0 * w0; a01 += v0 * w1;
                a10 += v1 * w0; a11 += v1 * w1;
            }
            hm[0][0][t] = leaky(a00); hm[0][1][t] = leaky(a01);
            hm[1][0][t] = leaky(a10); hm[1][1][t] = leaky(a11);
        }

        // ---------- stage 2: Wh1[t] = h_mix[t]·Wa1 ; Wh2[t] = h_mix[t]·Wa2 (butterfly)
        float Wh1[2][10], Wh2[2][10];
        #pragma unroll
        for (int t = 0; t < 10; t++) {
            #pragma unroll
            for (int e = 0; e < 2; e++) {
                float p1 = hm[e][0][t] * wa10 + hm[e][1][t] * wa11;
                float p2 = hm[e][0][t] * wa20 + hm[e][1][t] * wa21;
                #pragma unroll
                for (int off = 16; off > 0; off >>= 1) {
                    p1 += __shfl_xor_sync(FULLMASK, p1, off);
                    p2 += __shfl_xor_sync(FULLMASK, p2, off);
                }
                Wh1[e][t] = p1; Wh2[e][t] = p2;
            }
        }

        // ---------- stage 3: attention + MLP head -> obs_out (softmax over 5)
        #pragma unroll
        for (int e = 0; e < 2; e++) {
            // att1 row softmaxes: over i' of leaky(Wh1[5+j] + Wh2[i'])
            float mj[5], Sj[5];
            #pragma unroll
            for (int j = 0; j < 5; j++) {
                float v0 = leaky(Wh1[e][5 + j] + Wh2[e][0]);
                float v1 = leaky(Wh1[e][5 + j] + Wh2[e][1]);
                float v2 = leaky(Wh1[e][5 + j] + Wh2[e][2]);
                float v3 = leaky(Wh1[e][5 + j] + Wh2[e][3]);
                float v4 = leaky(Wh1[e][5 + j] + Wh2[e][4]);
                float m = fmaxf(fmaxf(fmaxf(v0, v1), fmaxf(v2, v3)), v4);
                float s = __expf(v0 - m) + __expf(v1 - m) + __expf(v2 - m)
                        + __expf(v3 - m) + __expf(v4 - m);
                mj[j] = m; Sj[j] = __frcp_rn(s);
            }
            #pragma unroll
            for (int i = 0; i < 5; i++) {
                float att[10];
                // att0 row i: softmax over j of leaky(Wh1[i] + Wh2[5+j])
                float u0 = leaky(Wh1[e][i] + Wh2[e][5]);
                float u1 = leaky(Wh1[e][i] + Wh2[e][6]);
                float u2 = leaky(Wh1[e][i] + Wh2[e][7]);
                float u3 = leaky(Wh1[e][i] + Wh2[e][8]);
                float u4 = leaky(Wh1[e][i] + Wh2[e][9]);
                float m0 = fmaxf(fmaxf(fmaxf(u0, u1), fmaxf(u2, u3)), u4);
                att[0] = __expf(u0 - m0); att[1] = __expf(u1 - m0); att[2] = __expf(u2 - m0);
                att[3] = __expf(u3 - m0); att[4] = __expf(u4 - m0);
                float r0 = __frcp_rn(att[0] + att[1] + att[2] + att[3] + att[4]);
                #pragma unroll
                for (int j = 0; j < 5; j++) att[j] *= r0;
                // att1^T columns
                #pragma unroll
                for (int j = 0; j < 5; j++)
                    att[5 + j] = __expf(leaky(Wh1[e][5 + j] + Wh2[e][i]) - mj[j]) * Sj[j];
                // hp1[i][l]
                float acc = smem[OFF_BO1 + l];
                #pragma unroll
                for (int j = 0; j < 10; j++) acc += att[j] * smem[OFF_WO1 + j * 32 + l];
                scr[e * 160 + i * 32 + l] = leaky(acc);
            }
        }
        __syncwarp();
        // hp2: (5,32)@(32,16)
        if (l < 16) {
            #pragma unroll
            for (int e = 0; e < 2; e++)
                #pragma unroll
                for (int i = 0; i < 5; i++) {
                    float acc = smem[OFF_BO2 + l];
                    #pragma unroll 8
                    for (int c = 0; c < 32; c++)
                        acc += scr[e * 160 + i * 32 + c] * smem[OFF_WO2 + c * 16 + l];
                    scr[320 + e * 80 + i * 16 + l] = leaky(acc);
                }
        }
        __syncwarp();
        // hp3: (5,16)@(16,1)
        if (l < 5) {
            #pragma unroll
            for (int e = 0; e < 2; e++) {
                float acc = smem[OFF_BO3];
                #pragma unroll
                for (int d = 0; d < 16; d++)
                    acc += scr[320 + e * 80 + l * 16 + d] * smem[OFF_WO3 + d];
                scr[480 + e * 8 + l] = leaky(acc);
            }
        }
        __syncwarp();
        // softmax over 5 -> obs_out (in place)
        if (l < 5) {
            #pragma unroll
            for (int e = 0; e < 2; e++) {
                float h0 = scr[480 + e * 8 + 0], h1 = scr[480 + e * 8 + 1];
                float h2 = scr[480 + e * 8 + 2], h3 = scr[480 + e * 8 + 3];
                float h4 = scr[480 + e * 8 + 4];
                float m = fmaxf(fmaxf(fmaxf(h0, h1), fmaxf(h2, h3)), h4);
                float s = __expf(h0 - m) + __expf(h1 - m) + __expf(h2 - m)
                        + __expf(h3 - m) + __expf(h4 - m);
                float my = (l == 0) ? h0 : (l == 1) ? h1 : (l == 2) ? h2 : (l == 3) ? h3 : h4;
                scr[480 + e * 8 + l] = __expf(my - m) * __frcp_rn(s);
            }
        }
        __syncwarp();

        // ---------- stage 4: fc1 (90 -> 64), x -> scr[0..128); h_in -> scr[128..256)
        float hin[2][2];
        #pragma unroll
        for (int e = 0; e < 2; e++) {
            const float* hrow = hidden + (size_t)(e0 + e) * 64;
            hin[e][0] = hrow[l]; hin[e][1] = hrow[32 + l];
            scr[128 + e * 64 + l]      = hin[e][0];
            scr[128 + e * 64 + 32 + l] = hin[e][1];
        }
        float x00 = smem[OFF_BFC1 + l], x01 = smem[OFF_BFC1 + 32 + l];
        float x10 = x00, x11 = x01;
        #pragma unroll 5
        for (int k = 0; k < 85; k++) {
            float w0 = smem[OFF_WFC1 + k * 64 + l];
            float w1 = smem[OFF_WFC1 + k * 64 + 32 + l];
            float s0 = (k < 32) ? ob[0][0] : ((k < 64) ? ob[0][1] : ob[0][2]);
            float s1 = (k < 32) ? ob[1][0] : ((k < 64) ? ob[1][1] : ob[1][2]);
            float v0 = __shfl_sync(FULLMASK, s0, k & 31);
            float v1 = __shfl_sync(FULLMASK, s1, k & 31);
            x00 += v0 * w0; x01 += v0 * w1;
            x10 += v1 * w0; x11 += v1 * w1;
        }
        #pragma unroll
        for (int k = 85; k < 90; k++) {
            float w0 = smem[OFF_WFC1 + k * 64 + l];
            float w1 = smem[OFF_WFC1 + k * 64 + 32 + l];
            float v0 = scr[480 + 0 * 8 + (k - 85)];
            float v1 = scr[480 + 1 * 8 + (k - 85)];
            x00 += v0 * w0; x01 += v0 * w1;
            x10 += v1 * w0; x11 += v1 * w1;
        }
        scr[l]           = fmaxf(x00, 0.f);
        scr[32 + l]      = fmaxf(x01, 0.f);
        scr[64 + l]      = fmaxf(x10, 0.f);
        scr[64 + 32 + l] = fmaxf(x11, 0.f);
        __syncwarp();

        // ---------- stage 5: GRU cell ----------
        float gacc[2][12]; // [e][0..5]=gi(r0,r1,z0,z1,n0,n1) [6..11]=gh(...)
        #pragma unroll
        for (int e = 0; e < 2; e++)
            #pragma unroll
            for (int g = 0; g < 3; g++) {
                gacc[e][2 * g + 0]     = smem[OFF_BIH + g * 64 + l];
                gacc[e][2 * g + 1]     = smem[OFF_BIH + g * 64 + 32 + l];
                gacc[e][6 + 2 * g + 0] = smem[OFF_BHH + g * 64 + l];
                gacc[e][6 + 2 * g + 1] = smem[OFF_BHH + g * 64 + 32 + l];
            }
        #pragma unroll 8
        for (int k = 0; k < 64; k++) {
            const float* wi = smem + OFF_WIHT + k * 192;
            const float* wh = smem + OFF_WHHT + k * 192;
            float wi0 = wi[l], wi1 = wi[32 + l], wi2 = wi[64 + l];
            float wi3 = wi[96 + l], wi4 = wi[128 + l], wi5 = wi[160 + l];
            float wh0 = wh[l], wh1 = wh[32 + l], wh2 = wh[64 + l];
            float wh3 = wh[96 + l], wh4 = wh[128 + l], wh5 = wh[160 + l];
            #pragma unroll
            for (int e = 0; e < 2; e++) {
                float xk = scr[e * 64 + k];
                float hk = scr[128 + e * 64 + k];
                gacc[e][0]  += xk * wi0; gacc[e][1]  += xk * wi1;
                gacc[e][2]  += xk * wi2; gacc[e][3]  += xk * wi3;
                gacc[e][4]  += xk * wi4; gacc[e][5]  += xk * wi5;
                gacc[e][6]  += hk * wh0; gacc[e][7]  += hk * wh1;
                gacc[e][8]  += hk * wh2; gacc[e][9]  += hk * wh3;
                gacc[e][10] += hk * wh4; gacc[e][11] += hk * wh5;
            }
        }
        #pragma unroll
        for (int e = 0; e < 2; e++) {
            float r0 = sigm(gacc[e][0] + gacc[e][6]);
            float r1 = sigm(gacc[e][1] + gacc[e][7]);
            float z0 = sigm(gacc[e][2] + gacc[e][8]);
            float z1 = sigm(gacc[e][3] + gacc[e][9]);
            float n0 = tanh_(gacc[e][4] + r0 * gacc[e][10]);
            float n1 = tanh_(gacc[e][5] + r1 * gacc[e][11]);
            float hn0 = (1.f - z0) * n0 + z0 * hin[e][0];
            float hn1 = (1.f - z1) * n1 + z1 * hin[e][1];
            outh[(size_t)(e0 + e) * 64 + l]      = hn0;
            outh[(size_t)(e0 + e) * 64 + 32 + l] = hn1;
            scr[128 + e * 64 + l]      = hn0;   // stage new h for fc2
            scr[128 + e * 64 + 32 + l] = hn1;
        }
        __syncwarp();
        // ---------- stage 6: q = h @ w_fc2 + b (lanes 0..4) ----------
        if (l < 5) {
            #pragma unroll
            for (int e = 0; e < 2; e++) {
                float acc = smem[OFF_BFC2 + l];
                #pragma unroll 8
                for (int k = 0; k < 64; k++)
                    acc += scr[128 + e * 64 + k] * smem[OFF_WFC2 + k * 5 + l];
                outq[(size_t)(e0 + e) * 5 + l] = acc;
            }
        }
        __syncwarp();
    }
}

extern "C" void kernel_launch(void* const* d_in, const int* in_sizes, int n_in,
                              void* d_out, int out_size)
{
    const float* obs    = (const float*)d_in[0];
    const float* hidden = (const float*)d_in[1];
    const float* w_in0  = (const float*)d_in[2];
    const float* b_in0  = (const float*)d_in[3];
    const float* w_in1  = (const float*)d_in[4];
    const float* b_in1  = (const float*)d_in[5];
    const float* w_in2  = (const float*)d_in[6];
    const float* b_in2  = (const float*)d_in[7];
    const float* W_     = (const float*)d_in[8];
    const float* a_     = (const float*)d_in[9];
    const float* w_o1   = (const float*)d_in[10];
    const float* b_o1   = (const float*)d_in[11];
    const float* w_o2   = (const float*)d_in[12];
    const float* b_o2   = (const float*)d_in[13];
    const float* w_o3   = (const float*)d_in[14];
    const float* b_o3   = (const float*)d_in[15];
    const float* w_fc1  = (const float*)d_in[16];
    const float* b_fc1  = (const float*)d_in[17];
    const float* w_ih   = (const float*)d_in[18];
    const float* w_hh   = (const float*)d_in[19];
    const float* b_ih   = (const float*)d_in[20];
    const float* b_hh   = (const float*)d_in[21];
    const float* w_fc2  = (const float*)d_in[22];
    const float* b_fc2  = (const float*)d_in[23];

    float* outq = (float*)d_out;                  // (B, 5) first
    float* outh = outq + (size_t)B_ * 5;          // then (B, 64)

    int nsm = 148;
    cudaDeviceGetAttribute(&nsm, cudaDevAttrMultiProcessorCount, 0);
    cudaFuncSetAttribute(atom_rnn_fused,
                         cudaFuncAttributeMaxDynamicSharedMemorySize, SMEM_BYTES);

    atom_rnn_fused<<<nsm, 384, SMEM_BYTES>>>(
        obs, hidden, w_in0, b_in0, w_in1, b_in1, w_in2, b_in2, W_, a_,
        w_o1, b_o1, w_o2, b_o2, w_o3, b_o3, w_fc1, b_fc1,
        w_ih, w_hh, b_ih, b_hh, w_fc2, b_fc2, outq, outh);
}

// round 8
// speedup vs baseline: 1.1125x; 1.1125x over previous
#include <cuda_runtime.h>

#define FULLMASK 0xffffffffu
typedef unsigned long long ull;

static constexpr int B_ = 65536;
static constexpr int OBS = 85;

// ---- shared memory layout (in floats) ----
static constexpr int OFF_WIN  = 0;                  // 3 * 8*64 = 1536
static constexpr int OFF_BIN  = OFF_WIN  + 1536;    // 3 * 64   = 192
static constexpr int OFF_WA   = OFF_BIN  + 192;     // 128 (Wa1|Wa2)
static constexpr int OFF_WO1  = OFF_WA   + 128;     // 10*32 = 320
static constexpr int OFF_BO1  = OFF_WO1  + 320;     // 32
static constexpr int OFF_WO2  = OFF_BO1  + 32;      // 32*16 = 512
static constexpr int OFF_BO2  = OFF_WO2  + 512;     // 16
static constexpr int OFF_WO3  = OFF_BO2  + 16;      // 16
static constexpr int OFF_BO3  = OFF_WO3  + 16;      // 1 (pad 16)
static constexpr int OFF_WFC1 = OFF_BO3  + 16;      // 90*64 = 5760
static constexpr int OFF_BFC1 = OFF_WFC1 + 5760;    // 64
static constexpr int OFF_WGRU = OFF_BFC1 + 64;      // 64*384 = 24576 (interleaved pairs)
static constexpr int OFF_BIH  = OFF_WGRU + 24576;   // 192
static constexpr int OFF_BHH  = OFF_BIH  + 192;     // 192
static constexpr int OFF_WFC2 = OFF_BHH  + 192;     // 64*5 = 320
static constexpr int OFF_BFC2 = OFF_WFC2 + 320;     // 5 (pad 16)
static constexpr int OFF_SCR  = OFF_BFC2 + 16;
// per-warp scratch: XH (64*18 = 1152 floats, dup-pair staging for GRU) + head (512)
static constexpr int XH_STRIDE   = 18;
static constexpr int SCR_PER_WARP = 1152 + 512;
static constexpr int SMEM_FLOATS = OFF_SCR + 12 * SCR_PER_WARP;
static constexpr int SMEM_BYTES  = SMEM_FLOATS * 4;

__device__ __forceinline__ float leaky(float x) { return x > 0.f ? x : 0.01f * x; }
__device__ __forceinline__ float sigm(float x)  { return __fdividef(1.f, 1.f + __expf(-x)); }
__device__ __forceinline__ float tanh_(float x) { return __fdividef(2.f, 1.f + __expf(-2.f * x)) - 1.f; }

__device__ __forceinline__ ull fpack(float lo, float hi) {
    ull r; asm("mov.b64 %0, {%1, %2};" : "=l"(r) : "f"(lo), "f"(hi)); return r;
}
__device__ __forceinline__ void funpack(ull v, float& lo, float& hi) {
    asm("mov.b64 {%0, %1}, %2;" : "=f"(lo), "=f"(hi) : "l"(v));
}
// d = a * b + d (packed 2x fp32)
__device__ __forceinline__ void ffma2(ull& d, ull a, ull b) {
    asm("fma.rn.f32x2 %0, %1, %2, %0;" : "+l"(d) : "l"(a), "l"(b));
}

__global__ void __launch_bounds__(384, 1)
atom_rnn_fused(const float* __restrict__ obs, const float* __restrict__ hidden,
               const float* __restrict__ w_in0, const float* __restrict__ b_in0,
               const float* __restrict__ w_in1, const float* __restrict__ b_in1,
               const float* __restrict__ w_in2, const float* __restrict__ b_in2,
               const float* __restrict__ W_,    const float* __restrict__ a_,
               const float* __restrict__ w_o1,  const float* __restrict__ b_o1,
               const float* __restrict__ w_o2,  const float* __restrict__ b_o2,
               const float* __restrict__ w_o3,  const float* __restrict__ b_o3,
               const float* __restrict__ w_fc1, const float* __restrict__ b_fc1,
               const float* __restrict__ w_ih,  const float* __restrict__ w_hh,
               const float* __restrict__ b_ih,  const float* __restrict__ b_hh,
               const float* __restrict__ w_fc2, const float* __restrict__ b_fc2,
               float* __restrict__ outq, float* __restrict__ outh)
{
    extern __shared__ float smem[];
    const int tid = threadIdx.x;

    // ================= cooperative weight staging ==========
    for (int i = tid; i < 512; i += 384) {
        smem[OFF_WIN + i]        = w_in0[i];
        smem[OFF_WIN + 512 + i]  = w_in1[i];
        smem[OFF_WIN + 1024 + i] = w_in2[i];
        smem[OFF_WO2 + i]        = w_o2[i];
    }
    for (int i = tid; i < 64; i += 384) {
        smem[OFF_BIN + i]       = b_in0[i];
        smem[OFF_BIN + 64 + i]  = b_in1[i];
        smem[OFF_BIN + 128 + i] = b_in2[i];
        smem[OFF_BFC1 + i]      = b_fc1[i];
    }
    if (tid < 128) { // Wa1[k] = sum_c W[k][c]*a[c] ; Wa2[k] = sum_c W[k][c]*a[64+c]
        int sel = tid >> 6, k = tid & 63;
        const float* av = a_ + sel * 64;
        const float* Wr = W_ + k * 64;
        float s = 0.f;
        #pragma unroll 8
        for (int c = 0; c < 64; c++) s += Wr[c] * av[c];
        smem[OFF_WA + sel * 64 + k] = s;
    }
    for (int i = tid; i < 320; i += 384) { smem[OFF_WO1 + i] = w_o1[i]; smem[OFF_WFC2 + i] = w_fc2[i]; }
    if (tid < 32) smem[OFF_BO1 + tid] = b_o1[tid];
    if (tid < 16) { smem[OFF_BO2 + tid] = b_o2[tid]; smem[OFF_WO3 + tid] = w_o3[tid]; }
    if (tid == 0) smem[OFF_BO3] = b_o3[0];
    if (tid < 5)  smem[OFF_BFC2 + tid] = b_fc2[tid];
    for (int i = tid; i < 5760; i += 384) smem[OFF_WFC1 + i] = w_fc1[i];
    // GRU weights, vector-interleaved: for each k, lane l reads 16B chunks:
    // chunk0=(wi0,wi1,wi2,wi3) chunk1=(wi4,wi5,wh0,wh1) chunk2=(wh2,wh3,wh4,wh5)
    // where wi(2g+c) = w_ih[g*64 + c*32 + l][k]
    for (int i = tid; i < 24576; i += 384) {
        int k = i / 384, r = i % 384;
        int chunk = r >> 7, t = r & 127;
        int ll = t >> 2, j = t & 3;
        int q = chunk * 4 + j;
        float v;
        if (q < 6)  v = w_ih[((q >> 1) * 64 + (q & 1) * 32 + ll) * 64 + k];
        else { int u = q - 6; v = w_hh[((u >> 1) * 64 + (u & 1) * 32 + ll) * 64 + k]; }
        smem[OFF_WGRU + i] = v;
    }
    for (int i = tid; i < 192; i += 384) { smem[OFF_BIH + i] = b_ih[i]; smem[OFF_BHH + i] = b_hh[i]; }
    __syncthreads();

    const int l    = tid & 31;
    const int warp = tid >> 5;
    float* XH = smem + OFF_SCR + warp * SCR_PER_WARP;    // 1152 floats
    float* hdm = XH + 1152;                              // 512 floats (head scratch)
    const int gwid = blockIdx.x * 12 + warp;
    const int nw   = gridDim.x * 12;

    const float wa10 = smem[OFF_WA + l],      wa11 = smem[OFF_WA + 32 + l];
    const float wa20 = smem[OFF_WA + 64 + l], wa21 = smem[OFF_WA + 96 + l];

    // GRU bias pairs (loop-invariant)
    const ull bgi0 = fpack(smem[OFF_BIH + l],       smem[OFF_BIH + 32 + l]);
    const ull bgi1 = fpack(smem[OFF_BIH + 64 + l],  smem[OFF_BIH + 96 + l]);
    const ull bgi2 = fpack(smem[OFF_BIH + 128 + l], smem[OFF_BIH + 160 + l]);
    const ull bgh0 = fpack(smem[OFF_BHH + l],       smem[OFF_BHH + 32 + l]);
    const ull bgh1 = fpack(smem[OFF_BHH + 64 + l],  smem[OFF_BHH + 96 + l]);
    const ull bgh2 = fpack(smem[OFF_BHH + 128 + l], smem[OFF_BHH + 160 + l]);

    for (int p = gwid; p < B_ / 4; p += nw) {
        const int e0 = p * 4;        // warp handles elements e0..e0+3
        float hinq[4][2];

        // ================= FRONT: two E=2 passes =================
        for (int ps = 0; ps < 2; ps++) {
            const int eb = e0 + ps * 2;

            float ob[2][3];
            #pragma unroll
            for (int e = 0; e < 2; e++) {
                const float* orow = obs + (size_t)(eb + e) * OBS;
                #pragma unroll
                for (int s = 0; s < 3; s++) {
                    int idx = s * 32 + l;
                    ob[e][s] = (idx < OBS) ? orow[idx] : 0.f;
                }
            }

            // stage 1: per-token input layer -> h_mix (cols l, 32+l)
            float hm[2][2][10];
            #pragma unroll
            for (int t = 0; t < 10; t++) {
                const int sel = (t < 5) ? 0 : ((t < 9) ? 1 : 2);
                const float* wsel = smem + OFF_WIN + sel * 512;
                float a00 = smem[OFF_BIN + sel * 64 + l];
                float a01 = smem[OFF_BIN + sel * 64 + 32 + l];
                float a10 = a00, a11 = a01;
                #pragma unroll
                for (int f = 0; f < 8; f++) {
                    const int ii = (t * 8 + f + 4) % 80;
                    float w0 = wsel[f * 64 + l];
                    float w1 = wsel[f * 64 + 32 + l];
                    float v0 = __shfl_sync(FULLMASK, ob[0][ii >> 5], ii & 31);
                    float v1 = __shfl_sync(FULLMASK, ob[1][ii >> 5], ii & 31);
                    a00 += v0 * w0; a01 += v0 * w1;
                    a10 += v1 * w0; a11 += v1 * w1;
                }
                hm[0][0][t] = leaky(a00); hm[0][1][t] = leaky(a01);
                hm[1][0][t] = leaky(a10); hm[1][1][t] = leaky(a11);
            }

            // stage 2: Wh1/Wh2 via butterfly reductions
            float Wh1[2][10], Wh2[2][10];
            #pragma unroll
            for (int t = 0; t < 10; t++) {
                #pragma unroll
                for (int e = 0; e < 2; e++) {
                    float p1 = hm[e][0][t] * wa10 + hm[e][1][t] * wa11;
                    float p2 = hm[e][0][t] * wa20 + hm[e][1][t] * wa21;
                    #pragma unroll
                    for (int off = 16; off > 0; off >>= 1) {
                        p1 += __shfl_xor_sync(FULLMASK, p1, off);
                        p2 += __shfl_xor_sync(FULLMASK, p2, off);
                    }
                    Wh1[e][t] = p1; Wh2[e][t] = p2;
                }
            }

            // stage 3: attention + head MLP
            #pragma unroll
            for (int e = 0; e < 2; e++) {
                float mj[5], Sj[5];
                #pragma unroll
                for (int j = 0; j < 5; j++) {
                    float v0 = leaky(Wh1[e][5 + j] + Wh2[e][0]);
                    float v1 = leaky(Wh1[e][5 + j] + Wh2[e][1]);
                    float v2 = leaky(Wh1[e][5 + j] + Wh2[e][2]);
                    float v3 = leaky(Wh1[e][5 + j] + Wh2[e][3]);
                    float v4 = leaky(Wh1[e][5 + j] + Wh2[e][4]);
                    float m = fmaxf(fmaxf(fmaxf(v0, v1), fmaxf(v2, v3)), v4);
                    float s = __expf(v0 - m) + __expf(v1 - m) + __expf(v2 - m)
                            + __expf(v3 - m) + __expf(v4 - m);
                    mj[j] = m; Sj[j] = __frcp_rn(s);
                }
                #pragma unroll
                for (int i = 0; i < 5; i++) {
                    float att[10];
                    float u0 = leaky(Wh1[e][i] + Wh2[e][5]);
                    float u1 = leaky(Wh1[e][i] + Wh2[e][6]);
                    float u2 = leaky(Wh1[e][i] + Wh2[e][7]);
                    float u3 = leaky(Wh1[e][i] + Wh2[e][8]);
                    float u4 = leaky(Wh1[e][i] + Wh2[e][9]);
                    float m0 = fmaxf(fmaxf(fmaxf(u0, u1), fmaxf(u2, u3)), u4);
                    att[0] = __expf(u0 - m0); att[1] = __expf(u1 - m0); att[2] = __expf(u2 - m0);
                    att[3] = __expf(u3 - m0); att[4] = __expf(u4 - m0);
                    float r0 = __frcp_rn(att[0] + att[1] + att[2] + att[3] + att[4]);
                    #pragma unroll
                    for (int j = 0; j < 5; j++) att[j] *= r0;
                    #pragma unroll
                    for (int j = 0; j < 5; j++)
                        att[5 + j] = __expf(leaky(Wh1[e][5 + j] + Wh2[e][i]) - mj[j]) * Sj[j];
                    float acc = smem[OFF_BO1 + l];
                    #pragma unroll
                    for (int j = 0; j < 10; j++) acc += att[j] * smem[OFF_WO1 + j * 32 + l];
                    hdm[e * 160 + i * 32 + l] = leaky(acc);
                }
            }
            __syncwarp();
            if (l < 16) {
                #pragma unroll
                for (int e = 0; e < 2; e++)
                    #pragma unroll
                    for (int i = 0; i < 5; i++) {
                        float acc = smem[OFF_BO2 + l];
                        #pragma unroll 8
                        for (int c = 0; c < 32; c++)
                            acc += hdm[e * 160 + i * 32 + c] * smem[OFF_WO2 + c * 16 + l];
                        hdm[320 + e * 80 + i * 16 + l] = leaky(acc);
                    }
            }
            __syncwarp();
            if (l < 5) {
                #pragma unroll
                for (int e = 0; e < 2; e++) {
                    float acc = smem[OFF_BO3];
                    #pragma unroll
                    for (int d = 0; d < 16; d++)
                        acc += hdm[320 + e * 80 + l * 16 + d] * smem[OFF_WO3 + d];
                    hdm[480 + e * 8 + l] = leaky(acc);
                }
            }
            __syncwarp();
            if (l < 5) {
                #pragma unroll
                for (int e = 0; e < 2; e++) {
                    float h0 = hdm[480 + e * 8 + 0], h1 = hdm[480 + e * 8 + 1];
                    float h2 = hdm[480 + e * 8 + 2], h3 = hdm[480 + e * 8 + 3];
                    float h4 = hdm[480 + e * 8 + 4];
                    float m = fmaxf(fmaxf(fmaxf(h0, h1), fmaxf(h2, h3)), h4);
                    float s = __expf(h0 - m) + __expf(h1 - m) + __expf(h2 - m)
                            + __expf(h3 - m) + __expf(h4 - m);
                    float my = (l == 0) ? h0 : (l == 1) ? h1 : (l == 2) ? h2 : (l == 3) ? h3 : h4;
                    hdm[480 + e * 8 + l] = __expf(my - m) * __frcp_rn(s);
                }
            }
            __syncwarp();

            // stage 4: fc1 (90 -> 64) + stage x/h into XH as dup-pairs
            #pragma unroll
            for (int e = 0; e < 2; e++) {
                const float* hrow = hidden + (size_t)(eb + e) * 64;
                hinq[ps * 2 + e][0] = hrow[l];
                hinq[ps * 2 + e][1] = hrow[32 + l];
            }
            float x00 = smem[OFF_BFC1 + l], x01 = smem[OFF_BFC1 + 32 + l];
            float x10 = x00, x11 = x01;
            #pragma unroll 5
            for (int k = 0; k < 85; k++) {
                float w0 = smem[OFF_WFC1 + k * 64 + l];
                float w1 = smem[OFF_WFC1 + k * 64 + 32 + l];
                float s0 = (k < 32) ? ob[0][0] : ((k < 64) ? ob[0][1] : ob[0][2]);
                float s1 = (k < 32) ? ob[1][0] : ((k < 64) ? ob[1][1] : ob[1][2]);
                float v0 = __shfl_sync(FULLMASK, s0, k & 31);
                float v1 = __shfl_sync(FULLMASK, s1, k & 31);
                x00 += v0 * w0; x01 += v0 * w1;
                x10 += v1 * w0; x11 += v1 * w1;
            }
            #pragma unroll
            for (int k = 85; k < 90; k++) {
                float w0 = smem[OFF_WFC1 + k * 64 + l];
                float w1 = smem[OFF_WFC1 + k * 64 + 32 + l];
                float v0 = hdm[480 + 0 * 8 + (k - 85)];
                float v1 = hdm[480 + 1 * 8 + (k - 85)];
                x00 += v0 * w0; x01 += v0 * w1;
                x10 += v1 * w0; x11 += v1 * w1;
            }
            x00 = fmaxf(x00, 0.f); x01 = fmaxf(x01, 0.f);
            x10 = fmaxf(x10, 0.f); x11 = fmaxf(x11, 0.f);
            // XH[k*18 + 2e]   = (x_e[k], x_e[k])   (dup pair)
            // XH[k*18 + 8+2e] = (h_e[k], h_e[k])
            {
                float* r0p = XH + l * XH_STRIDE;
                float* r1p = XH + (32 + l) * XH_STRIDE;
                *(ull*)(r0p + 4 * ps)     = fpack(x00, x00);
                *(ull*)(r0p + 4 * ps + 2) = fpack(x10, x10);
                *(ull*)(r1p + 4 * ps)     = fpack(x01, x01);
                *(ull*)(r1p + 4 * ps + 2) = fpack(x11, x11);
                *(ull*)(r0p + 8 + 4 * ps)     = fpack(hinq[ps*2+0][0], hinq[ps*2+0][0]);
                *(ull*)(r0p + 8 + 4 * ps + 2) = fpack(hinq[ps*2+1][0], hinq[ps*2+1][0]);
                *(ull*)(r1p + 8 + 4 * ps)     = fpack(hinq[ps*2+0][1], hinq[ps*2+0][1]);
                *(ull*)(r1p + 8 + 4 * ps + 2) = fpack(hinq[ps*2+1][1], hinq[ps*2+1][1]);
            }
            __syncwarp();
        } // passes

        // ================= GRU at E=4, fp32x2 packed =================
        ull acc[4][6];
        #pragma unroll
        for (int e = 0; e < 4; e++) {
            acc[e][0] = bgi0; acc[e][1] = bgi1; acc[e][2] = bgi2;
            acc[e][3] = bgh0; acc[e][4] = bgh1; acc[e][5] = bgh2;
        }
        {
            const float* wk = smem + OFF_WGRU + l * 4;
            const float* xh = XH;
            #pragma unroll 4
            for (int k = 0; k < 64; k++) {
                ulonglong2 wA = *(const ulonglong2*)(wk);        // (wi0,wi1),(wi2,wi3)
                ulonglong2 wB = *(const ulonglong2*)(wk + 128);  // (wi4,wi5),(wh0,wh1)
                ulonglong2 wC = *(const ulonglong2*)(wk + 256);  // (wh2,wh3),(wh4,wh5)
                wk += 384;
                #pragma unroll
                for (int e = 0; e < 4; e++) {
                    ull xd = *(const ull*)(xh + 2 * e);
                    ull hd = *(const ull*)(xh + 8 + 2 * e);
                    ffma2(acc[e][0], wA.x, xd);
                    ffma2(acc[e][1], wA.y, xd);
                    ffma2(acc[e][2], wB.x, xd);
                    ffma2(acc[e][3], wB.y, hd);
                    ffma2(acc[e][4], wC.x, hd);
                    ffma2(acc[e][5], wC.y, hd);
                }
                xh += XH_STRIDE;
            }
        }
        #pragma unroll
        for (int e = 0; e < 4; e++) {
            float gir0, gir1, giz0, giz1, gin0, gin1;
            float ghr0, ghr1, ghz0, ghz1, ghn0, ghn1;
            funpack(acc[e][0], gir0, gir1); funpack(acc[e][1], giz0, giz1);
            funpack(acc[e][2], gin0, gin1);
            funpack(acc[e][3], ghr0, ghr1); funpack(acc[e][4], ghz0, ghz1);
            funpack(acc[e][5], ghn0, ghn1);
            float r0 = sigm(gir0 + ghr0), r1 = sigm(gir1 + ghr1);
            float z0 = sigm(giz0 + ghz0), z1 = sigm(giz1 + ghz1);
            float n0 = tanh_(gin0 + r0 * ghn0), n1 = tanh_(gin1 + r1 * ghn1);
            float hn0 = (1.f - z0) * n0 + z0 * hinq[e][0];
            float hn1 = (1.f - z1) * n1 + z1 * hinq[e][1];
            outh[(size_t)(e0 + e) * 64 + l]      = hn0;
            outh[(size_t)(e0 + e) * 64 + 32 + l] = hn1;
            hdm[e * 68 + l]      = hn0;   // stride 68 -> conflict-free fc2 reads
            hdm[e * 68 + 32 + l] = hn1;
        }
        __syncwarp();

        // ================= fc2: q = h @ w_fc2 + b (20 lanes: e*5+j) ======
        if (l < 20) {
            int e = l / 5, j = l - e * 5;
            float acc2 = smem[OFF_BFC2 + j];
            #pragma unroll 8
            for (int k = 0; k < 64; k++)
                acc2 += hdm[e * 68 + k] * smem[OFF_WFC2 + k * 5 + j];
            outq[(size_t)(e0 + e) * 5 + j] = acc2;
        }
        __syncwarp();
    }
}

extern "C" void kernel_launch(void* const* d_in, const int* in_sizes, int n_in,
                              void* d_out, int out_size)
{
    const float* obs    = (const float*)d_in[0];
    const float* hidden = (const float*)d_in[1];
    const float* w_in0  = (const float*)d_in[2];
    const float* b_in0  = (const float*)d_in[3];
    const float* w_in1  = (const float*)d_in[4];
    const float* b_in1  = (const float*)d_in[5];
    const float* w_in2  = (const float*)d_in[6];
    const float* b_in2  = (const float*)d_in[7];
    const float* W_     = (const float*)d_in[8];
    const float* a_     = (const float*)d_in[9];
    const float* w_o1   = (const float*)d_in[10];
    const float* b_o1   = (const float*)d_in[11];
    const float* w_o2   = (const float*)d_in[12];
    const float* b_o2   = (const float*)d_in[13];
    const float* w_o3   = (const float*)d_in[14];
    const float* b_o3   = (const float*)d_in[15];
    const float* w_fc1  = (const float*)d_in[16];
    const float* b_fc1  = (const float*)d_in[17];
    const float* w_ih   = (const float*)d_in[18];
    const float* w_hh   = (const float*)d_in[19];
    const float* b_ih   = (const float*)d_in[20];
    const float* b_hh   = (const float*)d_in[21];
    const float* w_fc2  = (const float*)d_in[22];
    const float* b_fc2  = (const float*)d_in[23];

    float* outq = (float*)d_out;                  // (B, 5) first
    float* outh = outq + (size_t)B_ * 5;          // then (B, 64)

    int nsm = 148;
    cudaDeviceGetAttribute(&nsm, cudaDevAttrMultiProcessorCount, 0);
    cudaFuncSetAttribute(atom_rnn_fused,
                         cudaFuncAttributeMaxDynamicSharedMemorySize, SMEM_BYTES);

    atom_rnn_fused<<<nsm, 384, SMEM_BYTES>>>(
        obs, hidden, w_in0, b_in0, w_in1, b_in1, w_in2, b_in2, W_, a_,
        w_o1, b_o1, w_o2, b_o2, w_o3, b_o3, w_fc1, b_fc1,
        w_ih, w_hh, b_ih, b_hh, w_fc2, b_fc2, outq, outh);
}

// round 11
// speedup vs baseline: 1.2341x; 1.1093x over previous
#include <cuda_runtime.h>

#define FULLMASK 0xffffffffu
typedef unsigned long long ull;

static constexpr int B_ = 65536;
static constexpr int OBS = 85;

// ---- shared memory layout (in floats) ----
static constexpr int OFF_WIN  = 0;                  // 3 * 8*64 = 1536
static constexpr int OFF_BIN  = OFF_WIN  + 1536;    // 3 * 64   = 192
static constexpr int OFF_WA   = OFF_BIN  + 192;     // 128 (Wa1|Wa2)
static constexpr int OFF_WO1  = OFF_WA   + 128;     // 10*32 = 320
static constexpr int OFF_BO1  = OFF_WO1  + 320;     // 32
static constexpr int OFF_WO2  = OFF_BO1  + 32;      // 32*16 = 512
static constexpr int OFF_BO2  = OFF_WO2  + 512;     // 16
static constexpr int OFF_WO3  = OFF_BO2  + 16;      // 16
static constexpr int OFF_BO3  = OFF_WO3  + 16;      // 1 (pad 16)
static constexpr int OFF_WFC1 = OFF_BO3  + 16;      // 90*64 = 5760
static constexpr int OFF_BFC1 = OFF_WFC1 + 5760;    // 64
static constexpr int OFF_WGRU = OFF_BFC1 + 64;      // 64*384 = 24576 (interleaved pairs)
static constexpr int OFF_BIH  = OFF_WGRU + 24576;   // 192
static constexpr int OFF_BHH  = OFF_BIH  + 192;     // 192
static constexpr int OFF_WFC2 = OFF_BHH  + 192;     // 64*5 = 320
static constexpr int OFF_BFC2 = OFF_WFC2 + 320;     // 5 (pad 16)
static constexpr int OFF_SCR  = OFF_BFC2 + 16;      // 33888 (16B aligned)
// per-warp scratch: XH (64 rows * 20 floats = 1280, 16B-aligned rows) + head (544)
static constexpr int XH_STRIDE   = 20;
static constexpr int HDM_SIZE    = 544;
static constexpr int SCR_PER_WARP = 64 * XH_STRIDE + HDM_SIZE;   // 1824
static constexpr int SMEM_FLOATS = OFF_SCR + 12 * SCR_PER_WARP;
static constexpr int SMEM_BYTES  = SMEM_FLOATS * 4;

// head scratch (hdm) layout:
//   hp1:     e*164 + i*32 + c        (c<32, i<5, e<2)  -> max 322
//   hp2:     336 + e*84 + i*16 + col                  -> max 499
//   obs_out: 504 + e*8 + j                            -> max 516

__device__ __forceinline__ float leaky(float x) { return x > 0.f ? x : 0.01f * x; }
__device__ __forceinline__ float sigm(float x)  { return __fdividef(1.f, 1.f + __expf(-x)); }
__device__ __forceinline__ float tanh_(float x) { return __fdividef(2.f, 1.f + __expf(-2.f * x)) - 1.f; }

__device__ __forceinline__ ull fpack(float lo, float hi) {
    ull r; asm("mov.b64 %0, {%1, %2};" : "=l"(r) : "f"(lo), "f"(hi)); return r;
}
__device__ __forceinline__ void funpack(ull v, float& lo, float& hi) {
    asm("mov.b64 {%0, %1}, %2;" : "=f"(lo), "=f"(hi) : "l"(v));
}
// d = a * b + d (packed 2x fp32)
__device__ __forceinline__ void ffma2(ull& d, ull a, ull b) {
    asm("fma.rn.f32x2 %0, %1, %2, %0;" : "+l"(d) : "l"(a), "l"(b));
}

__global__ void __launch_bounds__(384, 1)
atom_rnn_fused(const float* __restrict__ obs, const float* __restrict__ hidden,
               const float* __restrict__ w_in0, const float* __restrict__ b_in0,
               const float* __restrict__ w_in1, const float* __restrict__ b_in1,
               const float* __restrict__ w_in2, const float* __restrict__ b_in2,
               const float* __restrict__ W_,    const float* __restrict__ a_,
               const float* __restrict__ w_o1,  const float* __restrict__ b_o1,
               const float* __restrict__ w_o2,  const float* __restrict__ b_o2,
               const float* __restrict__ w_o3,  const float* __restrict__ b_o3,
               const float* __restrict__ w_fc1, const float* __restrict__ b_fc1,
               const float* __restrict__ w_ih,  const float* __restrict__ w_hh,
               const float* __restrict__ b_ih,  const float* __restrict__ b_hh,
               const float* __restrict__ w_fc2, const float* __restrict__ b_fc2,
               float* __restrict__ outq, float* __restrict__ outh)
{
    extern __shared__ float smem[];
    const int tid = threadIdx.x;

    // ================= cooperative weight staging ==========
    for (int i = tid; i < 512; i += 384) {
        smem[OFF_WIN + i]        = w_in0[i];
        smem[OFF_WIN + 512 + i]  = w_in1[i];
        smem[OFF_WIN + 1024 + i] = w_in2[i];
        smem[OFF_WO2 + i]        = w_o2[i];
    }
    for (int i = tid; i < 64; i += 384) {
        smem[OFF_BIN + i]       = b_in0[i];
        smem[OFF_BIN + 64 + i]  = b_in1[i];
        smem[OFF_BIN + 128 + i] = b_in2[i];
        smem[OFF_BFC1 + i]      = b_fc1[i];
    }
    if (tid < 128) { // Wa1[k] = sum_c W[k][c]*a[c] ; Wa2[k] = sum_c W[k][c]*a[64+c]
        int sel = tid >> 6, k = tid & 63;
        const float* av = a_ + sel * 64;
        const float* Wr = W_ + k * 64;
        float s = 0.f;
        #pragma unroll 8
        for (int c = 0; c < 64; c++) s += Wr[c] * av[c];
        smem[OFF_WA + sel * 64 + k] = s;
    }
    for (int i = tid; i < 320; i += 384) { smem[OFF_WO1 + i] = w_o1[i]; smem[OFF_WFC2 + i] = w_fc2[i]; }
    if (tid < 32) smem[OFF_BO1 + tid] = b_o1[tid];
    if (tid < 16) { smem[OFF_BO2 + tid] = b_o2[tid]; smem[OFF_WO3 + tid] = w_o3[tid]; }
    if (tid == 0) smem[OFF_BO3] = b_o3[0];
    if (tid < 5)  smem[OFF_BFC2 + tid] = b_fc2[tid];
    for (int i = tid; i < 5760; i += 384) smem[OFF_WFC1 + i] = w_fc1[i];
    // GRU weights, vector-interleaved: for each k, lane l reads 16B chunks:
    // chunk0=(wi0,wi1,wi2,wi3) chunk1=(wi4,wi5,wh0,wh1) chunk2=(wh2,wh3,wh4,wh5)
    // where wi(2g+c) = w_ih[g*64 + c*32 + l][k]
    for (int i = tid; i < 24576; i += 384) {
        int k = i / 384, r = i % 384;
        int chunk = r >> 7, t = r & 127;
        int ll = t >> 2, j = t & 3;
        int q = chunk * 4 + j;
        float v;
        if (q < 6)  v = w_ih[((q >> 1) * 64 + (q & 1) * 32 + ll) * 64 + k];
        else { int u = q - 6; v = w_hh[((u >> 1) * 64 + (u & 1) * 32 + ll) * 64 + k]; }
        smem[OFF_WGRU + i] = v;
    }
    for (int i = tid; i < 192; i += 384) { smem[OFF_BIH + i] = b_ih[i]; smem[OFF_BHH + i] = b_hh[i]; }
    __syncthreads();

    const int l    = tid & 31;
    const int warp = tid >> 5;
    float* XH  = smem + OFF_SCR + warp * SCR_PER_WARP;   // 1280 floats
    float* hdm = XH + 64 * XH_STRIDE;                    // 544 floats (head scratch)
    const int gwid = blockIdx.x * 12 + warp;
    const int nw   = gridDim.x * 12;

    const float wa10 = smem[OFF_WA + l],      wa11 = smem[OFF_WA + 32 + l];
    const float wa20 = smem[OFF_WA + 64 + l], wa21 = smem[OFF_WA + 96 + l];

    // GRU bias pairs (loop-invariant)
    const ull bgi0 = fpack(smem[OFF_BIH + l],       smem[OFF_BIH + 32 + l]);
    const ull bgi1 = fpack(smem[OFF_BIH + 64 + l],  smem[OFF_BIH + 96 + l]);
    const ull bgi2 = fpack(smem[OFF_BIH + 128 + l], smem[OFF_BIH + 160 + l]);
    const ull bgh0 = fpack(smem[OFF_BHH + l],       smem[OFF_BHH + 32 + l]);
    const ull bgh1 = fpack(smem[OFF_BHH + 64 + l],  smem[OFF_BHH + 96 + l]);
    const ull bgh2 = fpack(smem[OFF_BHH + 128 + l], smem[OFF_BHH + 160 + l]);

    for (int p = gwid; p < B_ / 4; p += nw) {
        const int e0 = p * 4;        // warp handles elements e0..e0+3
        float hinq[4][2];

        // ================= FRONT: two E=2 passes =================
        for (int ps = 0; ps < 2; ps++) {
            const int eb = e0 + ps * 2;

            float ob[2][3];
            #pragma unroll
            for (int e = 0; e < 2; e++) {
                const float* orow = obs + (size_t)(eb + e) * OBS;
                #pragma unroll
                for (int s = 0; s < 3; s++) {
                    int idx = s * 32 + l;
                    ob[e][s] = (idx < OBS) ? orow[idx] : 0.f;
                }
            }

            // stage 1: per-token input layer -> h_mix (cols l, 32+l)
            float hm[2][2][10];
            #pragma unroll
            for (int t = 0; t < 10; t++) {
                const int sel = (t < 5) ? 0 : ((t < 9) ? 1 : 2);
                const float* wsel = smem + OFF_WIN + sel * 512;
                float a00 = smem[OFF_BIN + sel * 64 + l];
                float a01 = smem[OFF_BIN + sel * 64 + 32 + l];
                float a10 = a00, a11 = a01;
                #pragma unroll
                for (int f = 0; f < 8; f++) {
                    const int ii = (t * 8 + f + 4) % 80;
                    float w0 = wsel[f * 64 + l];
                    float w1 = wsel[f * 64 + 32 + l];
                    float v0 = __shfl_sync(FULLMASK, ob[0][ii >> 5], ii & 31);
                    float v1 = __shfl_sync(FULLMASK, ob[1][ii >> 5], ii & 31);
                    a00 += v0 * w0; a01 += v0 * w1;
                    a10 += v1 * w0; a11 += v1 * w1;
                }
                hm[0][0][t] = leaky(a00); hm[0][1][t] = leaky(a01);
                hm[1][0][t] = leaky(a10); hm[1][1][t] = leaky(a11);
            }

            // stage 2: Wh1/Wh2 via butterfly reductions
            float Wh1[2][10], Wh2[2][10];
            #pragma unroll
            for (int t = 0; t < 10; t++) {
                #pragma unroll
                for (int e = 0; e < 2; e++) {
                    float p1 = hm[e][0][t] * wa10 + hm[e][1][t] * wa11;
                    float p2 = hm[e][0][t] * wa20 + hm[e][1][t] * wa21;
                    #pragma unroll
                    for (int off = 16; off > 0; off >>= 1) {
                        p1 += __shfl_xor_sync(FULLMASK, p1, off);
                        p2 += __shfl_xor_sync(FULLMASK, p2, off);
                    }
                    Wh1[e][t] = p1; Wh2[e][t] = p2;
                }
            }

            // stage 3: attention + hp1 (lane = output col l for both e)
            #pragma unroll
            for (int e = 0; e < 2; e++) {
                float mj[5], Sj[5];
                #pragma unroll
                for (int j = 0; j < 5; j++) {
                    float v0 = leaky(Wh1[e][5 + j] + Wh2[e][0]);
                    float v1 = leaky(Wh1[e][5 + j] + Wh2[e][1]);
                    float v2 = leaky(Wh1[e][5 + j] + Wh2[e][2]);
                    float v3 = leaky(Wh1[e][5 + j] + Wh2[e][3]);
                    float v4 = leaky(Wh1[e][5 + j] + Wh2[e][4]);
                    float m = fmaxf(fmaxf(fmaxf(v0, v1), fmaxf(v2, v3)), v4);
                    float s = __expf(v0 - m) + __expf(v1 - m) + __expf(v2 - m)
                            + __expf(v3 - m) + __expf(v4 - m);
                    mj[j] = m; Sj[j] = __frcp_rn(s);
                }
                #pragma unroll
                for (int i = 0; i < 5; i++) {
                    float att[10];
                    float u0 = leaky(Wh1[e][i] + Wh2[e][5]);
                    float u1 = leaky(Wh1[e][i] + Wh2[e][6]);
                    float u2 = leaky(Wh1[e][i] + Wh2[e][7]);
                    float u3 = leaky(Wh1[e][i] + Wh2[e][8]);
                    float u4 = leaky(Wh1[e][i] + Wh2[e][9]);
                    float m0 = fmaxf(fmaxf(fmaxf(u0, u1), fmaxf(u2, u3)), u4);
                    att[0] = __expf(u0 - m0); att[1] = __expf(u1 - m0); att[2] = __expf(u2 - m0);
                    att[3] = __expf(u3 - m0); att[4] = __expf(u4 - m0);
                    float r0 = __frcp_rn(att[0] + att[1] + att[2] + att[3] + att[4]);
                    #pragma unroll
                    for (int j = 0; j < 5; j++) att[j] *= r0;
                    #pragma unroll
                    for (int j = 0; j < 5; j++)
                        att[5 + j] = __expf(leaky(Wh1[e][5 + j] + Wh2[e][i]) - mj[j]) * Sj[j];
                    float acc = smem[OFF_BO1 + l];
                    #pragma unroll
                    for (int j = 0; j < 10; j++) acc += att[j] * smem[OFF_WO1 + j * 32 + l];
                    hdm[e * 164 + i * 32 + l] = leaky(acc);   // hp1, padded e-stride
                }
            }
            __syncwarp();
            // hp2: all 32 lanes. lane -> (e2 = l>>4, col = l&15), 5 outputs each.
            {
                const int e2  = l >> 4;
                const int col = l & 15;
                const float* hp1 = hdm + e2 * 164;
                float acc2v[5];
                float b2 = smem[OFF_BO2 + col];
                #pragma unroll
                for (int i = 0; i < 5; i++) acc2v[i] = b2;
                #pragma unroll 8
                for (int c = 0; c < 32; c++) {
                    float w = smem[OFF_WO2 + c * 16 + col];
                    #pragma unroll
                    for (int i = 0; i < 5; i++)
                        acc2v[i] += hp1[i * 32 + c] * w;
                }
                #pragma unroll
                for (int i = 0; i < 5; i++)
                    hdm[336 + e2 * 84 + i * 16 + col] = leaky(acc2v[i]);
            }
            __syncwarp();
            if (l < 5) {
                #pragma unroll
                for (int e = 0; e < 2; e++) {
                    float acc = smem[OFF_BO3];
                    #pragma unroll
                    for (int d = 0; d < 16; d++)
                        acc += hdm[336 + e * 84 + l * 16 + d] * smem[OFF_WO3 + d];
                    hdm[504 + e * 8 + l] = leaky(acc);
                }
            }
            __syncwarp();
            if (l < 5) {
                #pragma unroll
                for (int e = 0; e < 2; e++) {
                    float h0 = hdm[504 + e * 8 + 0], h1 = hdm[504 + e * 8 + 1];
                    float h2 = hdm[504 + e * 8 + 2], h3 = hdm[504 + e * 8 + 3];
                    float h4 = hdm[504 + e * 8 + 4];
                    float m = fmaxf(fmaxf(fmaxf(h0, h1), fmaxf(h2, h3)), h4);
                    float s = __expf(h0 - m) + __expf(h1 - m) + __expf(h2 - m)
                            + __expf(h3 - m) + __expf(h4 - m);
                    float my = (l == 0) ? h0 : (l == 1) ? h1 : (l == 2) ? h2 : (l == 3) ? h3 : h4;
                    hdm[504 + e * 8 + l] = __expf(my - m) * __frcp_rn(s);
                }
            }
            __syncwarp();

            // stage 4: fc1 (90 -> 64) + stage x/h into XH as dup-pairs
            #pragma unroll
            for (int e = 0; e < 2; e++) {
                const float* hrow = hidden + (size_t)(eb + e) * 64;
                hinq[ps * 2 + e][0] = hrow[l];
                hinq[ps * 2 + e][1] = hrow[32 + l];
            }
            float x00 = smem[OFF_BFC1 + l], x01 = smem[OFF_BFC1 + 32 + l];
            float x10 = x00, x11 = x01;
            #pragma unroll 5
            for (int k = 0; k < 85; k++) {
                float w0 = smem[OFF_WFC1 + k * 64 + l];
                float w1 = smem[OFF_WFC1 + k * 64 + 32 + l];
                float s0 = (k < 32) ? ob[0][0] : ((k < 64) ? ob[0][1] : ob[0][2]);
                float s1 = (k < 32) ? ob[1][0] : ((k < 64) ? ob[1][1] : ob[1][2]);
                float v0 = __shfl_sync(FULLMASK, s0, k & 31);
                float v1 = __shfl_sync(FULLMASK, s1, k & 31);
                x00 += v0 * w0; x01 += v0 * w1;
                x10 += v1 * w0; x11 += v1 * w1;
            }
            #pragma unroll
            for (int k = 85; k < 90; k++) {
                float w0 = smem[OFF_WFC1 + k * 64 + l];
                float w1 = smem[OFF_WFC1 + k * 64 + 32 + l];
                float v0 = hdm[504 + 0 * 8 + (k - 85)];
                float v1 = hdm[504 + 1 * 8 + (k - 85)];
                x00 += v0 * w0; x01 += v0 * w1;
                x10 += v1 * w0; x11 += v1 * w1;
            }
            x00 = fmaxf(x00, 0.f); x01 = fmaxf(x01, 0.f);
            x10 = fmaxf(x10, 0.f); x11 = fmaxf(x11, 0.f);
            // XH row k (stride 20, 16B-aligned): [0..7]=x dup-pairs e0..e3, [8..15]=h dup-pairs
            {
                float* r0p = XH + l * XH_STRIDE;
                float* r1p = XH + (32 + l) * XH_STRIDE;
                *(ull*)(r0p + 4 * ps)     = fpack(x00, x00);
                *(ull*)(r0p + 4 * ps + 2) = fpack(x10, x10);
                *(ull*)(r1p + 4 * ps)     = fpack(x01, x01);
                *(ull*)(r1p + 4 * ps + 2) = fpack(x11, x11);
                *(ull*)(r0p + 8 + 4 * ps)     = fpack(hinq[ps*2+0][0], hinq[ps*2+0][0]);
                *(ull*)(r0p + 8 + 4 * ps + 2) = fpack(hinq[ps*2+1][0], hinq[ps*2+1][0]);
                *(ull*)(r1p + 8 + 4 * ps)     = fpack(hinq[ps*2+0][1], hinq[ps*2+0][1]);
                *(ull*)(r1p + 8 + 4 * ps + 2) = fpack(hinq[ps*2+1][1], hinq[ps*2+1][1]);
            }
            __syncwarp();
        } // passes

        // ================= GRU at E=4, fp32x2 packed =================
        ull acc[4][6];
        #pragma unroll
        for (int e = 0; e < 4; e++) {
            acc[e][0] = bgi0; acc[e][1] = bgi1; acc[e][2] = bgi2;
            acc[e][3] = bgh0; acc[e][4] = bgh1; acc[e][5] = bgh2;
        }
        {
            const float* wk = smem + OFF_WGRU + l * 4;
            const float* xh = XH;
            #pragma unroll 4
            for (int k = 0; k < 64; k++) {
                ulonglong2 wA = *(const ulonglong2*)(wk);        // (wi0,wi1),(wi2,wi3)
                ulonglong2 wB = *(const ulonglong2*)(wk + 128);  // (wi4,wi5),(wh0,wh1)
                ulonglong2 wC = *(const ulonglong2*)(wk + 256);  // (wh2,wh3),(wh4,wh5)
                wk += 384;
                ulonglong2 x01 = *(const ulonglong2*)(xh);       // xd(e0), xd(e1)
                ulonglong2 x23 = *(const ulonglong2*)(xh + 4);   // xd(e2), xd(e3)
                ulonglong2 h01 = *(const ulonglong2*)(xh + 8);   // hd(e0), hd(e1)
                ulonglong2 h23 = *(const ulonglong2*)(xh + 12);  // hd(e2), hd(e3)
                xh += XH_STRIDE;
                ull xd[4] = {x01.x, x01.y, x23.x, x23.y};
                ull hd[4] = {h01.x, h01.y, h23.x, h23.y};
                #pragma unroll
                for (int e = 0; e < 4; e++) {
                    ffma2(acc[e][0], wA.x, xd[e]);
                    ffma2(acc[e][1], wA.y, xd[e]);
                    ffma2(acc[e][2], wB.x, xd[e]);
                    ffma2(acc[e][3], wB.y, hd[e]);
                    ffma2(acc[e][4], wC.x, hd[e]);
                    ffma2(acc[e][5], wC.y, hd[e]);
                }
            }
        }
        #pragma unroll
        for (int e = 0; e < 4; e++) {
            float gir0, gir1, giz0, giz1, gin0, gin1;
            float ghr0, ghr1, ghz0, ghz1, ghn0, ghn1;
            funpack(acc[e][0], gir0, gir1); funpack(acc[e][1], giz0, giz1);
            funpack(acc[e][2], gin0, gin1);
            funpack(acc[e][3], ghr0, ghr1); funpack(acc[e][4], ghz0, ghz1);
            funpack(acc[e][5], ghn0, ghn1);
            float r0 = sigm(gir0 + ghr0), r1 = sigm(gir1 + ghr1);
            float z0 = sigm(giz0 + ghz0), z1 = sigm(giz1 + ghz1);
            float n0 = tanh_(gin0 + r0 * ghn0), n1 = tanh_(gin1 + r1 * ghn1);
            float hn0 = (1.f - z0) * n0 + z0 * hinq[e][0];
            float hn1 = (1.f - z1) * n1 + z1 * hinq[e][1];
            outh[(size_t)(e0 + e) * 64 + l]      = hn0;
            outh[(size_t)(e0 + e) * 64 + 32 + l] = hn1;
            hdm[e * 68 + l]      = hn0;   // stride 68 -> conflict-free fc2 reads
            hdm[e * 68 + 32 + l] = hn1;
        }
        __syncwarp();

        // ================= fc2: q = h @ w_fc2 + b (20 lanes: e*5+j) ======
        if (l < 20) {
            int e = l / 5, j = l - e * 5;
            float acc2 = smem[OFF_BFC2 + j];
            #pragma unroll 8
            for (int k = 0; k < 64; k++)
                acc2 += hdm[e * 68 + k] * smem[OFF_WFC2 + k * 5 + j];
            outq[(size_t)(e0 + e) * 5 + j] = acc2;
        }
        __syncwarp();
    }
}

extern "C" void kernel_launch(void* const* d_in, const int* in_sizes, int n_in,
                              void* d_out, int out_size)
{
    const float* obs    = (const float*)d_in[0];
    const float* hidden = (const float*)d_in[1];
    const float* w_in0  = (const float*)d_in[2];
    const float* b_in0  = (const float*)d_in[3];
    const float* w_in1  = (const float*)d_in[4];
    const float* b_in1  = (const float*)d_in[5];
    const float* w_in2  = (const float*)d_in[6];
    const float* b_in2  = (const float*)d_in[7];
    const float* W_     = (const float*)d_in[8];
    const float* a_     = (const float*)d_in[9];
    const float* w_o1   = (const float*)d_in[10];
    const float* b_o1   = (const float*)d_in[11];
    const float* w_o2   = (const float*)d_in[12];
    const float* b_o2   = (const float*)d_in[13];
    const float* w_o3   = (const float*)d_in[14];
    const float* b_o3   = (const float*)d_in[15];
    const float* w_fc1  = (const float*)d_in[16];
    const float* b_fc1  = (const float*)d_in[17];
    const float* w_ih   = (const float*)d_in[18];
    const float* w_hh   = (const float*)d_in[19];
    const float* b_ih   = (const float*)d_in[20];
    const float* b_hh   = (const float*)d_in[21];
    const float* w_fc2  = (const float*)d_in[22];
    const float* b_fc2  = (const float*)d_in[23];

    float* outq = (float*)d_out;                  // (B, 5) first
    float* outh = outq + (size_t)B_ * 5;          // then (B, 64)

    int nsm = 148;
    cudaDeviceGetAttribute(&nsm, cudaDevAttrMultiProcessorCount, 0);
    cudaFuncSetAttribute(atom_rnn_fused,
                         cudaFuncAttributeMaxDynamicSharedMemorySize, SMEM_BYTES);

    atom_rnn_fused<<<nsm, 384, SMEM_BYTES>>>(
        obs, hidden, w_in0, b_in0, w_in1, b_in1, w_in2, b_in2, W_, a_,
        w_o1, b_o1, w_o2, b_o2, w_o3, b_o3, w_fc1, b_fc1,
        w_ih, w_hh, b_ih, b_hh, w_fc2, b_fc2, outq, outh);
}